// round 3
// baseline (speedup 1.0000x reference)
#include <cuda_runtime.h>
#include <math.h>

#define D_IN 128
#define H1 256
#define H2 128
#define NMAX 150016
#define BMAX 16384
#define EMAX 4800000

// ---------------- scratch (device globals; no runtime alloc) ----------------
__device__ float g_y1[(size_t)NMAX * D_IN];    // A@x            [N,128]
__device__ float g_agg1[(size_t)NMAX * H1];    // (A@x)@W1+s b1  [N,256]
__device__ float g_t2[(size_t)NMAX * H2];      // bn1(agg1)@W2+b2[N,128]
__device__ float g_y2[(size_t)NMAX * H2];      // A@t2           [N,128]
__device__ float g_s[NMAX];                    // rowsum of vals
__device__ float g_comb[(size_t)BMAX * (2 * H2)];
__device__ float g_h[(size_t)BMAX * H2];
__device__ float g_sum1[H1], g_sq1[H1], g_scale1[H1], g_shift1[H1];
__device__ float g_sum2[H2], g_sq2[H2], g_scale2[H2], g_shift2[H2];
// CSR scratch
__device__ int g_cnt[NMAX];
__device__ int g_offs[NMAX + 1];
__device__ int g_offs_tmp[NMAX];
__device__ int2 g_csr[EMAX];   // (col, val bits)

static inline int cdiv(int a, int b) { return (a + b - 1) / b; }

// ---------------- packed fp32x2 helpers (sm_103a dual-FMA path) ----------------
__device__ __forceinline__ void ffma2(unsigned long long& d, unsigned long long a,
                                      unsigned long long b) {
    asm("fma.rn.f32x2 %0, %1, %2, %0;" : "+l"(d) : "l"(a), "l"(b));
}
__device__ __forceinline__ unsigned long long dup2(float x) {
    unsigned long long r;
    asm("mov.b64 %0, {%1, %1};" : "=l"(r) : "f"(x));
    return r;
}
__device__ __forceinline__ void unpack2(unsigned long long p, float& lo, float& hi) {
    asm("mov.b64 {%0, %1}, %2;" : "=f"(lo), "=f"(hi) : "l"(p));
}
__device__ __forceinline__ void lds_v2u64(unsigned long long& x, unsigned long long& y,
                                          const void* p) {
    unsigned addr = (unsigned)__cvta_generic_to_shared(p);
    asm volatile("ld.shared.v2.u64 {%0, %1}, [%2];" : "=l"(x), "=l"(y) : "r"(addr));
}

// ---------------- CSR build ----------------
__global__ void count_edges(const int* __restrict__ rows, int E) {
    int i = blockIdx.x * blockDim.x + threadIdx.x;
    if (i < E) atomicAdd(&g_cnt[__ldg(rows + i)], 1);
}

__global__ void __launch_bounds__(1024) scan_offsets(int N) {
    __shared__ int sums[1024];
    int t = threadIdx.x;
    int chunk = (N + 1023) / 1024;
    int lo = t * chunk;
    int hi = min(lo + chunk, N);
    int s = 0;
    for (int i = lo; i < hi; i++) s += g_cnt[i];
    sums[t] = s;
    __syncthreads();
    for (int off = 1; off < 1024; off <<= 1) {
        int add = (t >= off) ? sums[t - off] : 0;
        int v = sums[t];
        __syncthreads();
        sums[t] = v + add;
        __syncthreads();
    }
    int run = (t == 0) ? 0 : sums[t - 1];
    for (int i = lo; i < hi; i++) {
        g_offs[i] = run;
        g_offs_tmp[i] = run;
        run += g_cnt[i];
    }
    if (t == 1023) g_offs[N] = sums[1023];
}

__global__ void fill_csr(const int* __restrict__ rows, const int* __restrict__ cols,
                         const float* __restrict__ vals, int E) {
    int i = blockIdx.x * blockDim.x + threadIdx.x;
    if (i >= E) return;
    int r = __ldg(rows + i);
    int pos = atomicAdd(&g_offs_tmp[r], 1);
    g_csr[pos] = make_int2(__ldg(cols + i), __float_as_int(__ldg(vals + i)));
}

// ---------------- layer-1 aggregation: y1[r] = sum val*x[col]; s[r] = sum val ----------------
__global__ void agg_emb(const float* __restrict__ uemb, const float* __restrict__ iemb,
                        int n_users, int N) {
    int row = (blockIdx.x * blockDim.x + threadIdx.x) >> 5;
    int lane = threadIdx.x & 31;
    if (row >= N) return;
    int start = g_offs[row];
    int end = g_offs[row + 1];
    float4 acc = make_float4(0.f, 0.f, 0.f, 0.f);
    float sv = 0.f;
#pragma unroll 4
    for (int i = start; i < end; i++) {
        int2 cv = __ldg(&g_csr[i]);
        float v = __int_as_float(cv.y);
        const float* src = (cv.x < n_users) ? (uemb + (size_t)cv.x * D_IN)
                                            : (iemb + (size_t)(cv.x - n_users) * D_IN);
        float4 x = __ldg(((const float4*)src) + lane);
        acc.x = fmaf(v, x.x, acc.x);
        acc.y = fmaf(v, x.y, acc.y);
        acc.z = fmaf(v, x.z, acc.z);
        acc.w = fmaf(v, x.w, acc.w);
        sv += v;
    }
    *(float4*)(g_y1 + (size_t)row * D_IN + lane * 4) = acc;
    if (lane == 0) g_s[row] = sv;
}

// ---------------- layer-2 aggregation: y2[r] = sum val*t2[col] ----------------
__global__ void agg_dense(int N) {
    int row = (blockIdx.x * blockDim.x + threadIdx.x) >> 5;
    int lane = threadIdx.x & 31;
    if (row >= N) return;
    int start = g_offs[row];
    int end = g_offs[row + 1];
    float4 acc = make_float4(0.f, 0.f, 0.f, 0.f);
#pragma unroll 4
    for (int i = start; i < end; i++) {
        int2 cv = __ldg(&g_csr[i]);
        float v = __int_as_float(cv.y);
        float4 x = __ldg(((const float4*)(g_t2 + (size_t)cv.x * H2)) + lane);
        acc.x = fmaf(v, x.x, acc.x);
        acc.y = fmaf(v, x.y, acc.y);
        acc.z = fmaf(v, x.z, acc.z);
        acc.w = fmaf(v, x.w, acc.w);
    }
    *(float4*)(g_y2 + (size_t)row * H2 + lane * 4) = acc;
}

// ---------------- column sums / sum of squares ----------------
__global__ void colstats(const float* __restrict__ X, int M, int C,
                         float* __restrict__ osum, float* __restrict__ osq) {
    int col = threadIdx.x % C;
    int sub = threadIdx.x / C;
    int nsub = blockDim.x / C;
    float s = 0.f, q = 0.f;
    for (int r = blockIdx.x * nsub + sub; r < M; r += gridDim.x * nsub) {
        float v = X[(size_t)r * C + col];
        s += v;
        q += v * v;
    }
    atomicAdd(&osum[col], s);
    atomicAdd(&osq[col], q);
}

// ---------------- BN finalize ----------------
__global__ void bn_fin(const float* __restrict__ isum, const float* __restrict__ isq,
                       const float* __restrict__ g, const float* __restrict__ beta,
                       float invM, int C, float* __restrict__ oscale, float* __restrict__ oshift) {
    int c = threadIdx.x;
    if (c < C) {
        float mu = isum[c] * invM;
        float var = isq[c] * invM - mu * mu;
        float rs = rsqrtf(var + 1e-5f);
        float sc = rs * g[c];
        oscale[c] = sc;
        oshift[c] = beta[c] - mu * sc;
    }
}

// ---------------- SGEMM 128x128x8, 256 threads, 8x8 micro (FFMA2), double-buffered ----------------
template <bool TRANSA, bool SROWBIAS, bool RELUEPI>
__global__ void __launch_bounds__(256) sgemm_k(
    const float* __restrict__ A, const float* __restrict__ Bw, float* __restrict__ C,
    int M, int Nn, int Kk,
    const float* __restrict__ bias, const float* __restrict__ srow,
    const float* __restrict__ tscale, const float* __restrict__ tshift) {
    const int BM = 128, BN = 128, BK = 8;
    __shared__ float As[2][BK][BM];
    __shared__ float Bs[2][BK][BN];
    __shared__ float s_sc[256], s_sh[256];

    int tid = threadIdx.x;
    int m0 = blockIdx.x * BM;
    int n0 = blockIdx.y * BN;

    if (TRANSA) {
        for (int k = tid; k < Kk; k += 256) {
            s_sc[k] = tscale[k];
            s_sh[k] = tshift[k];
        }
    }
    __syncthreads();

    int arow = tid >> 1;
    int acol = (tid & 1) * 4;
    int am = m0 + arow;
    int brow = tid >> 5;
    int bcol = (tid & 31) * 4;
    int ty = tid >> 4, tx = tid & 15;

    unsigned long long acc2[8][4];
#pragma unroll
    for (int i = 0; i < 8; i++)
#pragma unroll
        for (int jp = 0; jp < 4; jp++) acc2[i][jp] = 0ull;

    int T = Kk / BK;
    float4 ra, rb;

#define LOAD_TILES(t)                                                              \
    {                                                                              \
        int gk = (t) * BK + acol;                                                  \
        ra = make_float4(0.f, 0.f, 0.f, 0.f);                                      \
        if (am < M) ra = __ldg((const float4*)(A + (size_t)am * Kk + gk));         \
        if (TRANSA) {                                                              \
            ra.x = fmaxf(0.f, fmaf(ra.x, s_sc[gk + 0], s_sh[gk + 0]));             \
            ra.y = fmaxf(0.f, fmaf(ra.y, s_sc[gk + 1], s_sh[gk + 1]));             \
            ra.z = fmaxf(0.f, fmaf(ra.z, s_sc[gk + 2], s_sh[gk + 2]));             \
            ra.w = fmaxf(0.f, fmaf(ra.w, s_sc[gk + 3], s_sh[gk + 3]));             \
        }                                                                          \
        rb = __ldg((const float4*)(Bw + (size_t)((t) * BK + brow) * Nn + n0 + bcol)); \
    }

#define STORE_TILES(buf)                          \
    {                                             \
        As[buf][acol + 0][arow] = ra.x;           \
        As[buf][acol + 1][arow] = ra.y;           \
        As[buf][acol + 2][arow] = ra.z;           \
        As[buf][acol + 3][arow] = ra.w;           \
        *(float4*)&Bs[buf][brow][bcol] = rb;      \
    }

    LOAD_TILES(0)
    STORE_TILES(0)
    __syncthreads();

    for (int t = 0; t < T; t++) {
        int cur = t & 1;
        if (t + 1 < T) LOAD_TILES(t + 1)
#pragma unroll
        for (int k = 0; k < BK; k++) {
            float a[8];
            unsigned long long bp[4], ad[8];
            *(float4*)&a[0] = *(const float4*)&As[cur][k][ty * 8];
            *(float4*)&a[4] = *(const float4*)&As[cur][k][ty * 8 + 4];
            lds_v2u64(bp[0], bp[1], &Bs[cur][k][tx * 8]);
            lds_v2u64(bp[2], bp[3], &Bs[cur][k][tx * 8 + 4]);
#pragma unroll
            for (int i = 0; i < 8; i++) ad[i] = dup2(a[i]);
#pragma unroll
            for (int i = 0; i < 8; i++)
#pragma unroll
                for (int jp = 0; jp < 4; jp++) ffma2(acc2[i][jp], ad[i], bp[jp]);
        }
        if (t + 1 < T) {
            STORE_TILES((t + 1) & 1)
            __syncthreads();
        }
    }

#pragma unroll
    for (int i = 0; i < 8; i++) {
        int gm = m0 + ty * 8 + i;
        if (gm >= M) continue;
        float sv = 1.0f;
        if (SROWBIAS) sv = __ldg(srow + gm);
        int gn = n0 + tx * 8;
        float o[8];
#pragma unroll
        for (int jp = 0; jp < 4; jp++) unpack2(acc2[i][jp], o[2 * jp], o[2 * jp + 1]);
#pragma unroll
        for (int j = 0; j < 8; j++) {
            float v = o[j] + sv * __ldg(bias + gn + j);
            if (RELUEPI) v = fmaxf(v, 0.f);
            o[j] = v;
        }
        *(float4*)(C + (size_t)gm * Nn + gn) = *(float4*)&o[0];
        *(float4*)(C + (size_t)gm * Nn + gn + 4) = *(float4*)&o[4];
    }
#undef LOAD_TILES
#undef STORE_TILES
}

// ---------------- gather batch rows, apply BN2+relu ----------------
__global__ void gather_comb(const int* __restrict__ uidx, const int* __restrict__ iidx,
                            int n_users) {
    int b = blockIdx.x;
    int k = threadIdx.x;  // 0..255
    int node, kk;
    if (k < H2) {
        node = __ldg(uidx + b);
        kk = k;
    } else {
        node = n_users + __ldg(iidx + b);
        kk = k - H2;
    }
    float v = g_y2[(size_t)node * H2 + kk];
    g_comb[(size_t)b * (2 * H2) + k] = fmaxf(0.f, fmaf(v, g_scale2[kk], g_shift2[kk]));
}

// ---------------- final dot ----------------
__global__ void final_dot(const float* __restrict__ P2, const float* __restrict__ pb2,
                          float* __restrict__ out, int B) {
    int w = (blockIdx.x * blockDim.x + threadIdx.x) >> 5;
    int lane = threadIdx.x & 31;
    if (w >= B) return;
    float4 h = *(const float4*)(g_h + (size_t)w * H2 + lane * 4);
    float4 p = __ldg(((const float4*)P2) + lane);
    float d = h.x * p.x + h.y * p.y + h.z * p.z + h.w * p.w;
#pragma unroll
    for (int o = 16; o; o >>= 1) d += __shfl_xor_sync(0xFFFFFFFFu, d, o);
    if (lane == 0) out[w] = d + __ldg(pb2);
}

// ---------------- launch ----------------
extern "C" void kernel_launch(void* const* d_in, const int* in_sizes, int n_in,
                              void* d_out, int out_size) {
    const int* uidx = (const int*)d_in[0];
    const int* iidx = (const int*)d_in[1];
    const int* erow = (const int*)d_in[2];
    const int* ecol = (const int*)d_in[3];
    const float* eval = (const float*)d_in[4];
    const float* uemb = (const float*)d_in[5];
    const float* iemb = (const float*)d_in[6];
    const float* W1 = (const float*)d_in[7];
    const float* b1 = (const float*)d_in[8];
    const float* g1 = (const float*)d_in[9];
    const float* beta1 = (const float*)d_in[10];
    const float* W2 = (const float*)d_in[11];
    const float* b2 = (const float*)d_in[12];
    const float* g2 = (const float*)d_in[13];
    const float* beta2 = (const float*)d_in[14];
    const float* P1 = (const float*)d_in[15];
    const float* pb1 = (const float*)d_in[16];
    const float* P2 = (const float*)d_in[17];
    const float* pb2 = (const float*)d_in[18];
    float* out = (float*)d_out;

    int B = in_sizes[0];
    int E = in_sizes[2];
    int n_users = in_sizes[5] / D_IN;
    int n_items = in_sizes[6] / D_IN;
    int N = n_users + n_items;

    void *y1p, *agg1p, *t2p, *combp, *hp, *sp;
    void *sum1p, *sq1p, *scale1p, *shift1p, *sum2p, *sq2p, *scale2p, *shift2p;
    void *cntp, *y2p;
    cudaGetSymbolAddress(&y1p, g_y1);
    cudaGetSymbolAddress(&agg1p, g_agg1);
    cudaGetSymbolAddress(&t2p, g_t2);
    cudaGetSymbolAddress(&y2p, g_y2);
    cudaGetSymbolAddress(&sp, g_s);
    cudaGetSymbolAddress(&combp, g_comb);
    cudaGetSymbolAddress(&hp, g_h);
    cudaGetSymbolAddress(&sum1p, g_sum1);
    cudaGetSymbolAddress(&sq1p, g_sq1);
    cudaGetSymbolAddress(&scale1p, g_scale1);
    cudaGetSymbolAddress(&shift1p, g_shift1);
    cudaGetSymbolAddress(&sum2p, g_sum2);
    cudaGetSymbolAddress(&sq2p, g_sq2);
    cudaGetSymbolAddress(&scale2p, g_scale2);
    cudaGetSymbolAddress(&shift2p, g_shift2);
    cudaGetSymbolAddress(&cntp, g_cnt);

    cudaMemsetAsync(cntp, 0, (size_t)N * sizeof(int));
    cudaMemsetAsync(sum1p, 0, H1 * sizeof(float));
    cudaMemsetAsync(sq1p, 0, H1 * sizeof(float));
    cudaMemsetAsync(sum2p, 0, H2 * sizeof(float));
    cudaMemsetAsync(sq2p, 0, H2 * sizeof(float));

    // ----- CSR build (shared by both layers) -----
    count_edges<<<cdiv(E, 256), 256>>>(erow, E);
    scan_offsets<<<1, 1024>>>(N);
    fill_csr<<<cdiv(E, 256), 256>>>(erow, ecol, eval, E);

    // ----- Layer 1: aggregate (d=128) then transform to h1=256 -----
    agg_emb<<<cdiv(N, 8), 256>>>(uemb, iemb, n_users, N);
    sgemm_k<false, true, false><<<dim3(cdiv(N, 128), H1 / 128), 256>>>(
        (const float*)y1p, W1, (float*)agg1p, N, H1, D_IN, b1, (const float*)sp,
        nullptr, nullptr);
    colstats<<<1024, 256>>>((const float*)agg1p, N, H1, (float*)sum1p, (float*)sq1p);
    bn_fin<<<1, 256>>>((const float*)sum1p, (const float*)sq1p, g1, beta1, 1.0f / N, H1,
                       (float*)scale1p, (float*)shift1p);

    // ----- Layer 2: transform (256->128) then aggregate -----
    sgemm_k<true, false, false><<<dim3(cdiv(N, 128), H2 / 128), 256>>>(
        (const float*)agg1p, W2, (float*)t2p, N, H2, H1, b2, nullptr,
        (const float*)scale1p, (const float*)shift1p);
    agg_dense<<<cdiv(N, 8), 256>>>(N);
    colstats<<<1024, 256>>>((const float*)y2p, N, H2, (float*)sum2p, (float*)sq2p);
    bn_fin<<<1, 256>>>((const float*)sum2p, (const float*)sq2p, g2, beta2, 1.0f / N, H2,
                       (float*)scale2p, (float*)shift2p);

    // ----- Prediction head -----
    gather_comb<<<B, 256>>>(uidx, iidx, n_users);
    sgemm_k<false, false, true><<<dim3(cdiv(B, 128), H2 / 128), 256>>>(
        (const float*)combp, P1, (float*)hp, B, H2, 2 * H2, pb1, nullptr, nullptr,
        nullptr);
    final_dot<<<cdiv(B, 8), 256>>>(P2, pb2, out, B);
}

// round 4
// speedup vs baseline: 1.3792x; 1.3792x over previous
#include <cuda_runtime.h>
#include <math.h>

#define D_IN 128
#define H1 256
#define H2 128
#define NMAX 150016
#define BMAX 16384
#define EMAX 4800000

// ---------------- scratch (device globals; no runtime alloc) ----------------
__device__ float g_y1[(size_t)NMAX * D_IN];    // A@x            [N,128]
__device__ float g_agg1[(size_t)NMAX * H1];    // (A@x)@W1+s b1  [N,256]
__device__ float g_t2[(size_t)NMAX * H2];      // bn1(agg1)@W2+b2[N,128]
__device__ float g_y2[(size_t)NMAX * H2];      // A@t2           [N,128]
__device__ float g_s[NMAX];                    // rowsum of vals
__device__ float g_comb[(size_t)BMAX * (2 * H2)];
__device__ float g_h[(size_t)BMAX * H2];
__device__ float g_sum1[H1], g_sq1[H1], g_scale1[H1], g_shift1[H1];
__device__ float g_sum2[H2], g_sq2[H2], g_scale2[H2], g_shift2[H2];
// CSR scratch
__device__ int g_cnt[NMAX];
__device__ int g_offs[NMAX + 1];
__device__ int g_offs_tmp[NMAX];
__device__ int2 g_csr[EMAX];   // (col, val bits)

static inline int cdiv(int a, int b) { return (a + b - 1) / b; }

// ---------------- tf32 helpers ----------------
__device__ __forceinline__ unsigned f2tf32(float x) {
    unsigned r;
    asm("cvt.rna.tf32.f32 %0, %1;" : "=r"(r) : "f"(x));
    return r;
}
__device__ __forceinline__ void mma_tf32(float* c, const unsigned* a, const unsigned* b) {
    asm volatile(
        "mma.sync.aligned.m16n8k8.row.col.f32.tf32.tf32.f32 "
        "{%0,%1,%2,%3}, {%4,%5,%6,%7}, {%8,%9}, {%0,%1,%2,%3};"
        : "+f"(c[0]), "+f"(c[1]), "+f"(c[2]), "+f"(c[3])
        : "r"(a[0]), "r"(a[1]), "r"(a[2]), "r"(a[3]), "r"(b[0]), "r"(b[1]));
}

// ---------------- CSR build ----------------
__global__ void count_edges(const int* __restrict__ rows, int E) {
    int i = blockIdx.x * blockDim.x + threadIdx.x;
    if (i < E) atomicAdd(&g_cnt[__ldg(rows + i)], 1);
}

__global__ void __launch_bounds__(1024) scan_offsets(int N) {
    __shared__ int sums[1024];
    int t = threadIdx.x;
    int chunk = (N + 1023) / 1024;
    int lo = t * chunk;
    int hi = min(lo + chunk, N);
    int s = 0;
    for (int i = lo; i < hi; i++) s += g_cnt[i];
    sums[t] = s;
    __syncthreads();
    for (int off = 1; off < 1024; off <<= 1) {
        int add = (t >= off) ? sums[t - off] : 0;
        int v = sums[t];
        __syncthreads();
        sums[t] = v + add;
        __syncthreads();
    }
    int run = (t == 0) ? 0 : sums[t - 1];
    for (int i = lo; i < hi; i++) {
        g_offs[i] = run;
        g_offs_tmp[i] = run;
        run += g_cnt[i];
    }
    if (t == 1023) g_offs[N] = sums[1023];
}

__global__ void fill_csr(const int* __restrict__ rows, const int* __restrict__ cols,
                         const float* __restrict__ vals, int E) {
    int i = blockIdx.x * blockDim.x + threadIdx.x;
    if (i >= E) return;
    int r = __ldg(rows + i);
    int pos = atomicAdd(&g_offs_tmp[r], 1);
    g_csr[pos] = make_int2(__ldg(cols + i), __float_as_int(__ldg(vals + i)));
}

// ---------------- layer-1 aggregation ----------------
__global__ void agg_emb(const float* __restrict__ uemb, const float* __restrict__ iemb,
                        int n_users, int N) {
    int row = (blockIdx.x * blockDim.x + threadIdx.x) >> 5;
    int lane = threadIdx.x & 31;
    if (row >= N) return;
    int start = g_offs[row];
    int end = g_offs[row + 1];
    float4 acc = make_float4(0.f, 0.f, 0.f, 0.f);
    float sv = 0.f;
#pragma unroll 4
    for (int i = start; i < end; i++) {
        int2 cv = __ldg(&g_csr[i]);
        float v = __int_as_float(cv.y);
        const float* src = (cv.x < n_users) ? (uemb + (size_t)cv.x * D_IN)
                                            : (iemb + (size_t)(cv.x - n_users) * D_IN);
        float4 x = __ldg(((const float4*)src) + lane);
        acc.x = fmaf(v, x.x, acc.x);
        acc.y = fmaf(v, x.y, acc.y);
        acc.z = fmaf(v, x.z, acc.z);
        acc.w = fmaf(v, x.w, acc.w);
        sv += v;
    }
    *(float4*)(g_y1 + (size_t)row * D_IN + lane * 4) = acc;
    if (lane == 0) g_s[row] = sv;
}

// ---------------- layer-2 aggregation ----------------
__global__ void agg_dense(int N) {
    int row = (blockIdx.x * blockDim.x + threadIdx.x) >> 5;
    int lane = threadIdx.x & 31;
    if (row >= N) return;
    int start = g_offs[row];
    int end = g_offs[row + 1];
    float4 acc = make_float4(0.f, 0.f, 0.f, 0.f);
#pragma unroll 4
    for (int i = start; i < end; i++) {
        int2 cv = __ldg(&g_csr[i]);
        float v = __int_as_float(cv.y);
        float4 x = __ldg(((const float4*)(g_t2 + (size_t)cv.x * H2)) + lane);
        acc.x = fmaf(v, x.x, acc.x);
        acc.y = fmaf(v, x.y, acc.y);
        acc.z = fmaf(v, x.z, acc.z);
        acc.w = fmaf(v, x.w, acc.w);
    }
    *(float4*)(g_y2 + (size_t)row * H2 + lane * 4) = acc;
}

// ---------------- column sums / sum of squares ----------------
__global__ void colstats(const float* __restrict__ X, int M, int C,
                         float* __restrict__ osum, float* __restrict__ osq) {
    int col = threadIdx.x % C;
    int sub = threadIdx.x / C;
    int nsub = blockDim.x / C;
    float s = 0.f, q = 0.f;
    for (int r = blockIdx.x * nsub + sub; r < M; r += gridDim.x * nsub) {
        float v = X[(size_t)r * C + col];
        s += v;
        q += v * v;
    }
    atomicAdd(&osum[col], s);
    atomicAdd(&osq[col], q);
}

// ---------------- BN finalize ----------------
__global__ void bn_fin(const float* __restrict__ isum, const float* __restrict__ isq,
                       const float* __restrict__ g, const float* __restrict__ beta,
                       float invM, int C, float* __restrict__ oscale, float* __restrict__ oshift) {
    int c = threadIdx.x;
    if (c < C) {
        float mu = isum[c] * invM;
        float var = isq[c] * invM - mu * mu;
        float rs = rsqrtf(var + 1e-5f);
        float sc = rs * g[c];
        oscale[c] = sc;
        oshift[c] = beta[c] - mu * sc;
    }
}

// ---------------- TF32 tensor-core GEMM: 128x128x16 CTA, 8 warps (32x64 each) ----------------
// C[m,n] = (TRANSA? relu(A*sc+sh) : A)[m,:] @ Bw[:,n] + (SROWBIAS? srow[m]:1)*bias[n]
template <bool TRANSA, bool SROWBIAS, bool RELUEPI>
__global__ void __launch_bounds__(256) gemm_tc(
    const float* __restrict__ A, const float* __restrict__ Bw, float* __restrict__ C,
    int M, int Nn, int Kk,
    const float* __restrict__ bias, const float* __restrict__ srow,
    const float* __restrict__ tscale, const float* __restrict__ tshift) {
    const int BM = 128, BN = 128, BK = 16;
    __shared__ unsigned As[2][BM][BK + 4];   // [m][k]
    __shared__ unsigned Bs[2][BK][BN + 4];   // [k][n]
    __shared__ float s_sc[256], s_sh[256];

    int tid = threadIdx.x;
    int lane = tid & 31;
    int w = tid >> 5;
    int m0 = blockIdx.x * BM;
    int n0 = blockIdx.y * BN;
    int warp_m = (w & 3) * 32;   // 4 warps down M
    int warp_n = (w >> 2) * 64;  // 2 warps across N

    if (TRANSA) {
        for (int k = tid; k < Kk; k += 256) {
            s_sc[k] = tscale[k];
            s_sh[k] = tshift[k];
        }
        __syncthreads();
    }

    // global-load coordinates
    int ar0 = tid >> 1;                // A: rows tid/2 and tid/2+... (2 float4 per thread)
    int aq0 = (tid & 1) * 2;           // which float4-pair start? we use f=tid, f+256
    // We use: f in {tid, tid+256}: row=f>>2, colq=f&3
    int br_;
    (void)ar0; (void)aq0; (void)br_;

    float acc[2][8][4];
#pragma unroll
    for (int mf = 0; mf < 2; mf++)
#pragma unroll
        for (int nf = 0; nf < 8; nf++)
#pragma unroll
            for (int c = 0; c < 4; c++) acc[mf][nf][c] = 0.f;

    int T = Kk / BK;
    float4 ra[2], rb[2];

#define G_LOAD(t)                                                                     \
    {                                                                                 \
        int k0 = (t) * BK;                                                            \
        _Pragma("unroll") for (int r = 0; r < 2; r++) {                               \
            int f = tid + r * 256;                                                    \
            int row = f >> 2, colq = f & 3;                                           \
            ra[r] = make_float4(0.f, 0.f, 0.f, 0.f);                                  \
            if (m0 + row < M)                                                         \
                ra[r] = __ldg((const float4*)(A + (size_t)(m0 + row) * Kk + k0 + colq * 4)); \
        }                                                                             \
        _Pragma("unroll") for (int r = 0; r < 2; r++) {                               \
            int f = tid + r * 256;                                                    \
            int row = f >> 5, colq = f & 31;                                          \
            rb[r] = __ldg((const float4*)(Bw + (size_t)(k0 + row) * Nn + n0 + colq * 4)); \
        }                                                                             \
    }

#define S_STORE(buf, t)                                                               \
    {                                                                                 \
        int k0 = (t) * BK;                                                            \
        _Pragma("unroll") for (int r = 0; r < 2; r++) {                               \
            int f = tid + r * 256;                                                    \
            int row = f >> 2, colq = f & 3;                                           \
            float vx = ra[r].x, vy = ra[r].y, vz = ra[r].z, vw = ra[r].w;             \
            if (TRANSA) {                                                             \
                int gk = k0 + colq * 4;                                               \
                vx = fmaxf(0.f, fmaf(vx, s_sc[gk + 0], s_sh[gk + 0]));                \
                vy = fmaxf(0.f, fmaf(vy, s_sc[gk + 1], s_sh[gk + 1]));                \
                vz = fmaxf(0.f, fmaf(vz, s_sc[gk + 2], s_sh[gk + 2]));                \
                vw = fmaxf(0.f, fmaf(vw, s_sc[gk + 3], s_sh[gk + 3]));                \
            }                                                                         \
            uint4 p = make_uint4(f2tf32(vx), f2tf32(vy), f2tf32(vz), f2tf32(vw));     \
            *(uint4*)&As[buf][row][colq * 4] = p;                                     \
        }                                                                             \
        _Pragma("unroll") for (int r = 0; r < 2; r++) {                               \
            int f = tid + r * 256;                                                    \
            int row = f >> 5, colq = f & 31;                                          \
            uint4 p = make_uint4(f2tf32(rb[r].x), f2tf32(rb[r].y), f2tf32(rb[r].z),   \
                                 f2tf32(rb[r].w));                                    \
            *(uint4*)&Bs[buf][row][colq * 4] = p;                                     \
        }                                                                             \
    }

    G_LOAD(0)
    S_STORE(0, 0)
    __syncthreads();

    for (int t = 0; t < T; t++) {
        int cur = t & 1;
        if (t + 1 < T) G_LOAD(t + 1)
#pragma unroll
        for (int ks = 0; ks < 2; ks++) {
            int k0 = ks * 8;
            unsigned afr[2][4], bfr[8][2];
            int arow = warp_m + (lane >> 2);
            int akc = k0 + (lane & 3);
#pragma unroll
            for (int mf = 0; mf < 2; mf++) {
                int r = arow + mf * 16;
                afr[mf][0] = As[cur][r][akc];
                afr[mf][1] = As[cur][r + 8][akc];
                afr[mf][2] = As[cur][r][akc + 4];
                afr[mf][3] = As[cur][r + 8][akc + 4];
            }
            int bcol = warp_n + (lane >> 2);
            int bkr = k0 + (lane & 3);
#pragma unroll
            for (int nf = 0; nf < 8; nf++) {
                bfr[nf][0] = Bs[cur][bkr][bcol + nf * 8];
                bfr[nf][1] = Bs[cur][bkr + 4][bcol + nf * 8];
            }
#pragma unroll
            for (int mf = 0; mf < 2; mf++)
#pragma unroll
                for (int nf = 0; nf < 8; nf++) mma_tf32(acc[mf][nf], afr[mf], bfr[nf]);
        }
        if (t + 1 < T) {
            S_STORE((t + 1) & 1, t + 1)
            __syncthreads();
        }
    }

    // epilogue
#pragma unroll
    for (int mf = 0; mf < 2; mf++) {
        int r0 = m0 + warp_m + mf * 16 + (lane >> 2);
#pragma unroll
        for (int half = 0; half < 2; half++) {
            int gr = r0 + half * 8;
            if (gr >= M) continue;
            float sv = 1.0f;
            if (SROWBIAS) sv = __ldg(srow + gr);
#pragma unroll
            for (int nf = 0; nf < 8; nf++) {
                int gc = n0 + warp_n + nf * 8 + 2 * (lane & 3);
                float v0 = acc[mf][nf][half * 2 + 0] + sv * __ldg(bias + gc);
                float v1 = acc[mf][nf][half * 2 + 1] + sv * __ldg(bias + gc + 1);
                if (RELUEPI) {
                    v0 = fmaxf(v0, 0.f);
                    v1 = fmaxf(v1, 0.f);
                }
                *(float2*)(C + (size_t)gr * Nn + gc) = make_float2(v0, v1);
            }
        }
    }
#undef G_LOAD
#undef S_STORE
}

// ---------------- gather batch rows, apply BN2+relu ----------------
__global__ void gather_comb(const int* __restrict__ uidx, const int* __restrict__ iidx,
                            int n_users) {
    int b = blockIdx.x;
    int k = threadIdx.x;  // 0..255
    int node, kk;
    if (k < H2) {
        node = __ldg(uidx + b);
        kk = k;
    } else {
        node = n_users + __ldg(iidx + b);
        kk = k - H2;
    }
    float v = g_y2[(size_t)node * H2 + kk];
    g_comb[(size_t)b * (2 * H2) + k] = fmaxf(0.f, fmaf(v, g_scale2[kk], g_shift2[kk]));
}

// ---------------- final dot ----------------
__global__ void final_dot(const float* __restrict__ P2, const float* __restrict__ pb2,
                          float* __restrict__ out, int B) {
    int w = (blockIdx.x * blockDim.x + threadIdx.x) >> 5;
    int lane = threadIdx.x & 31;
    if (w >= B) return;
    float4 h = *(const float4*)(g_h + (size_t)w * H2 + lane * 4);
    float4 p = __ldg(((const float4*)P2) + lane);
    float d = h.x * p.x + h.y * p.y + h.z * p.z + h.w * p.w;
#pragma unroll
    for (int o = 16; o; o >>= 1) d += __shfl_xor_sync(0xFFFFFFFFu, d, o);
    if (lane == 0) out[w] = d + __ldg(pb2);
}

// ---------------- launch ----------------
extern "C" void kernel_launch(void* const* d_in, const int* in_sizes, int n_in,
                              void* d_out, int out_size) {
    const int* uidx = (const int*)d_in[0];
    const int* iidx = (const int*)d_in[1];
    const int* erow = (const int*)d_in[2];
    const int* ecol = (const int*)d_in[3];
    const float* eval = (const float*)d_in[4];
    const float* uemb = (const float*)d_in[5];
    const float* iemb = (const float*)d_in[6];
    const float* W1 = (const float*)d_in[7];
    const float* b1 = (const float*)d_in[8];
    const float* g1 = (const float*)d_in[9];
    const float* beta1 = (const float*)d_in[10];
    const float* W2 = (const float*)d_in[11];
    const float* b2 = (const float*)d_in[12];
    const float* g2 = (const float*)d_in[13];
    const float* beta2 = (const float*)d_in[14];
    const float* P1 = (const float*)d_in[15];
    const float* pb1 = (const float*)d_in[16];
    const float* P2 = (const float*)d_in[17];
    const float* pb2 = (const float*)d_in[18];
    float* out = (float*)d_out;

    int B = in_sizes[0];
    int E = in_sizes[2];
    int n_users = in_sizes[5] / D_IN;
    int n_items = in_sizes[6] / D_IN;
    int N = n_users + n_items;

    void *y1p, *agg1p, *t2p, *combp, *hp, *sp;
    void *sum1p, *sq1p, *scale1p, *shift1p, *sum2p, *sq2p, *scale2p, *shift2p;
    void *cntp, *y2p;
    cudaGetSymbolAddress(&y1p, g_y1);
    cudaGetSymbolAddress(&agg1p, g_agg1);
    cudaGetSymbolAddress(&t2p, g_t2);
    cudaGetSymbolAddress(&y2p, g_y2);
    cudaGetSymbolAddress(&sp, g_s);
    cudaGetSymbolAddress(&combp, g_comb);
    cudaGetSymbolAddress(&hp, g_h);
    cudaGetSymbolAddress(&sum1p, g_sum1);
    cudaGetSymbolAddress(&sq1p, g_sq1);
    cudaGetSymbolAddress(&scale1p, g_scale1);
    cudaGetSymbolAddress(&shift1p, g_shift1);
    cudaGetSymbolAddress(&sum2p, g_sum2);
    cudaGetSymbolAddress(&sq2p, g_sq2);
    cudaGetSymbolAddress(&scale2p, g_scale2);
    cudaGetSymbolAddress(&shift2p, g_shift2);
    cudaGetSymbolAddress(&cntp, g_cnt);

    cudaMemsetAsync(cntp, 0, (size_t)N * sizeof(int));
    cudaMemsetAsync(sum1p, 0, H1 * sizeof(float));
    cudaMemsetAsync(sq1p, 0, H1 * sizeof(float));
    cudaMemsetAsync(sum2p, 0, H2 * sizeof(float));
    cudaMemsetAsync(sq2p, 0, H2 * sizeof(float));

    // ----- CSR build (shared by both layers) -----
    count_edges<<<cdiv(E, 256), 256>>>(erow, E);
    scan_offsets<<<1, 1024>>>(N);
    fill_csr<<<cdiv(E, 256), 256>>>(erow, ecol, eval, E);

    // ----- Layer 1: aggregate (d=128) then transform to h1=256 -----
    agg_emb<<<cdiv(N, 8), 256>>>(uemb, iemb, n_users, N);
    gemm_tc<false, true, false><<<dim3(cdiv(N, 128), H1 / 128), 256>>>(
        (const float*)y1p, W1, (float*)agg1p, N, H1, D_IN, b1, (const float*)sp,
        nullptr, nullptr);
    colstats<<<1024, 256>>>((const float*)agg1p, N, H1, (float*)sum1p, (float*)sq1p);
    bn_fin<<<1, 256>>>((const float*)sum1p, (const float*)sq1p, g1, beta1, 1.0f / N, H1,
                       (float*)scale1p, (float*)shift1p);

    // ----- Layer 2: transform (256->128) then aggregate -----
    gemm_tc<true, false, false><<<dim3(cdiv(N, 128), H2 / 128), 256>>>(
        (const float*)agg1p, W2, (float*)t2p, N, H2, H1, b2, nullptr,
        (const float*)scale1p, (const float*)shift1p);
    agg_dense<<<cdiv(N, 8), 256>>>(N);
    colstats<<<1024, 256>>>((const float*)y2p, N, H2, (float*)sum2p, (float*)sq2p);
    bn_fin<<<1, 256>>>((const float*)sum2p, (const float*)sq2p, g2, beta2, 1.0f / N, H2,
                       (float*)scale2p, (float*)shift2p);

    // ----- Prediction head -----
    gather_comb<<<B, 256>>>(uidx, iidx, n_users);
    gemm_tc<false, false, true><<<dim3(cdiv(B, 128), H2 / 128), 256>>>(
        (const float*)combp, P1, (float*)hp, B, H2, 2 * H2, pb1, nullptr, nullptr,
        nullptr);
    final_dot<<<cdiv(B, 8), 256>>>(P2, pb2, out, B);
}